// round 1
// baseline (speedup 1.0000x reference)
#include <cuda_runtime.h>

#define NA 100000
#define NBND 200000
#define MAXNB 6
#define AF 133
#define BF 147
#define H 256
#define NM 4096
#define MF 200
#define XDIM (H + MF)   /* 456 */
#define F1 512
#define F2 256

// ---------------- scratch (device globals; no allocations allowed) ----------
__device__ float g_inputs[NBND * H];   // pre-relu bond inputs
__device__ float g_msgA[NBND * H];
__device__ float g_msgB[NBND * H];
__device__ float g_amsg[NA * H];
__device__ float g_atomh[NA * H];
__device__ float g_molx[NM * XDIM];
__device__ float g_h1[NM * F1];

// ---------------- A-side loaders -------------------------------------------
struct ALoadDirect {
    const float* __restrict__ A;
    int ld;
    __device__ __forceinline__ float operator()(int r, int k) const {
        return A[(long long)r * ld + k];
    }
};

// row r of A = a_message[b2a[r]] - message[b2revb[r]]   (K = 256)
struct ALoadMsg {
    const float* __restrict__ amsg;
    const float* __restrict__ msg;
    const int* __restrict__ b2a;
    const int* __restrict__ b2revb;
    __device__ __forceinline__ float operator()(int r, int k) const {
        return amsg[(long long)b2a[r] * H + k] - msg[(long long)b2revb[r] * H + k];
    }
};

// row r of A = concat(f_atoms[r] (133), a_message[r] (256))   (K = 389)
struct ALoadConcat {
    const float* __restrict__ fa;
    const float* __restrict__ amsg;
    __device__ __forceinline__ float operator()(int r, int k) const {
        return (k < AF) ? fa[(long long)r * AF + k]
                        : amsg[(long long)r * H + (k - AF)];
    }
};

// ---------------- epilogues -------------------------------------------------
struct EpiBond {            // store pre-relu inputs AND relu(message0)
    float* __restrict__ inputs;
    float* __restrict__ msg;
    __device__ __forceinline__ void operator()(int r, int n, float acc) const {
        long long o = (long long)r * H + n;
        inputs[o] = acc;
        msg[o] = fmaxf(acc, 0.f);
    }
};
struct EpiMsg {             // relu(inputs + acc)
    const float* __restrict__ inputs;
    float* __restrict__ out;
    __device__ __forceinline__ void operator()(int r, int n, float acc) const {
        long long o = (long long)r * H + n;
        out[o] = fmaxf(inputs[o] + acc, 0.f);
    }
};
struct EpiBias {            // relu(acc + bias[n]), arbitrary out ld
    const float* __restrict__ bias;
    float* __restrict__ out;
    int ld;
    __device__ __forceinline__ void operator()(int r, int n, float acc) const {
        out[(long long)r * ld + n] = fmaxf(acc + bias[n], 0.f);
    }
};

// ---------------- generic fp32 register-tiled GEMM --------------------------
// C[M,N] = A[M,K] @ B[K,N] (B row-major [K,N]), BM=BN=128, BK=16, 256 threads,
// 8x8 per-thread accumulators. A via functor (fused gathers), result via epi.
template <class AL, class EP>
__global__ __launch_bounds__(256) void gemm_k(AL al, EP ep,
                                              const float* __restrict__ B,
                                              int M, int N, int K) {
    __shared__ float As[16][128];
    __shared__ float Bs[16][128];

    const int bm = blockIdx.x * 128;
    const int bn = blockIdx.y * 128;
    const int tid = threadIdx.x;
    const int arow = tid >> 1;          // 0..127
    const int akoff = (tid & 1) * 8;    // 0 or 8
    const int ty = tid >> 4;            // 0..15  -> rows ty*8..+8
    const int tx = tid & 15;            // 0..15  -> cols tx*8..+8

    float acc[8][8];
#pragma unroll
    for (int i = 0; i < 8; i++)
#pragma unroll
        for (int j = 0; j < 8; j++) acc[i][j] = 0.f;

    const int rA = bm + arow;
    const bool rAok = (rA < M);

    for (int k0 = 0; k0 < K; k0 += 16) {
        // load A tile (transposed into As[k][m])
#pragma unroll
        for (int j = 0; j < 8; j++) {
            int k = akoff + j;
            float v = (rAok && (k0 + k) < K) ? al(rA, k0 + k) : 0.f;
            As[k][arow] = v;
        }
        // load B tile (coalesced along n)
#pragma unroll
        for (int j = 0; j < 8; j++) {
            int idx = tid + j * 256;
            int kk = idx >> 7;
            int n = idx & 127;
            float v = ((k0 + kk) < K) ? B[(long long)(k0 + kk) * N + bn + n] : 0.f;
            Bs[kk][n] = v;
        }
        __syncthreads();

#pragma unroll
        for (int kk = 0; kk < 16; kk++) {
            float4 a0 = *(const float4*)&As[kk][ty * 8];
            float4 a1 = *(const float4*)&As[kk][ty * 8 + 4];
            float4 b0 = *(const float4*)&Bs[kk][tx * 8];
            float4 b1 = *(const float4*)&Bs[kk][tx * 8 + 4];
            float a[8] = {a0.x, a0.y, a0.z, a0.w, a1.x, a1.y, a1.z, a1.w};
            float b[8] = {b0.x, b0.y, b0.z, b0.w, b1.x, b1.y, b1.z, b1.w};
#pragma unroll
            for (int i = 0; i < 8; i++)
#pragma unroll
                for (int j = 0; j < 8; j++) acc[i][j] = fmaf(a[i], b[j], acc[i][j]);
        }
        __syncthreads();
    }

#pragma unroll
    for (int i = 0; i < 8; i++) {
        int r = bm + ty * 8 + i;
        if (r < M) {
#pragma unroll
            for (int j = 0; j < 8; j++) ep(r, bn + tx * 8 + j, acc[i][j]);
        }
    }
}

// ---------------- neighbor aggregation: amsg[a] = sum_j msg[a2b[a][j]] ------
__global__ __launch_bounds__(256) void aggregate_k(const float* __restrict__ msg,
                                                   const int* __restrict__ a2b,
                                                   float* __restrict__ amsg) {
    int i = blockIdx.x * blockDim.x + threadIdx.x;   // over NA * (H/4)
    if (i >= NA * (H / 4)) return;
    int a = i >> 6;
    int c = (i & 63) * 4;
    const int* nb = &a2b[a * MAXNB];
    float4 s = make_float4(0.f, 0.f, 0.f, 0.f);
#pragma unroll
    for (int j = 0; j < MAXNB; j++) {
        int b = nb[j];
        float4 v = *(const float4*)&msg[(long long)b * H + c];
        s.x += v.x; s.y += v.y; s.z += v.z; s.w += v.w;
    }
    *(float4*)&amsg[(long long)a * H + c] = s;
}

// ---------------- per-molecule mean (atom2mol sorted) + feature concat ------
__device__ __forceinline__ int lower_bound_i(const int* __restrict__ a, int n, int v) {
    int lo = 0, hi = n;
    while (lo < hi) {
        int mid = (lo + hi) >> 1;
        if (a[mid] < v) lo = mid + 1; else hi = mid;
    }
    return lo;
}

__global__ __launch_bounds__(256) void segmean_k(const float* __restrict__ atomh,
                                                 const int* __restrict__ atom2mol,
                                                 const float* __restrict__ molfeat,
                                                 float* __restrict__ molx) {
    int m = blockIdx.x;
    int tid = threadIdx.x;
    int start = lower_bound_i(atom2mol, NA, m);
    int end = lower_bound_i(atom2mol, NA, m + 1);
    int cnt = end - start;
    float inv = 1.f / (float)max(cnt, 1);
    float s = 0.f;
    for (int a = start; a < end; a++) s += atomh[(long long)a * H + tid];
    molx[(long long)m * XDIM + tid] = s * inv;
    if (tid < MF) molx[(long long)m * XDIM + H + tid] = molfeat[(long long)m * MF + tid];
}

// ---------------- launch ----------------------------------------------------
extern "C" void kernel_launch(void* const* d_in, const int* in_sizes, int n_in,
                              void* d_out, int out_size) {
    (void)in_sizes; (void)n_in; (void)out_size;
    const float* f_atoms   = (const float*)d_in[0];
    const float* f_bonds   = (const float*)d_in[1];
    const int*   a2b       = (const int*)d_in[2];
    const int*   b2a       = (const int*)d_in[3];
    const int*   b2revb    = (const int*)d_in[4];
    const int*   atom2mol  = (const int*)d_in[5];
    const float* mol_feat  = (const float*)d_in[6];
    const float* W_i       = (const float*)d_in[7];
    const float* W_h       = (const float*)d_in[8];
    const float* W_o_w     = (const float*)d_in[9];
    const float* W_o_b     = (const float*)d_in[10];
    const float* W1        = (const float*)d_in[11];
    const float* b1        = (const float*)d_in[12];
    const float* W2        = (const float*)d_in[13];
    const float* b2        = (const float*)d_in[14];
    float* out = (float*)d_out;

    float *p_inputs, *p_msgA, *p_msgB, *p_amsg, *p_atomh, *p_molx, *p_h1;
    cudaGetSymbolAddress((void**)&p_inputs, g_inputs);
    cudaGetSymbolAddress((void**)&p_msgA,   g_msgA);
    cudaGetSymbolAddress((void**)&p_msgB,   g_msgB);
    cudaGetSymbolAddress((void**)&p_amsg,   g_amsg);
    cudaGetSymbolAddress((void**)&p_atomh,  g_atomh);
    cudaGetSymbolAddress((void**)&p_molx,   g_molx);
    cudaGetSymbolAddress((void**)&p_h1,     g_h1);

    dim3 blk(256);

    // 1) inputs = f_bonds @ W_i ; msgA = relu(inputs)
    {
        dim3 grid((NBND + 127) / 128, H / 128);
        gemm_k<<<grid, blk>>>(ALoadDirect{f_bonds, BF},
                              EpiBond{p_inputs, p_msgA},
                              W_i, NBND, H, BF);
    }

    int aggBlocks = (NA * (H / 4) + 255) / 256;

    // 2) depth iteration 1: msgA -> msgB
    aggregate_k<<<aggBlocks, blk>>>(p_msgA, a2b, p_amsg);
    {
        dim3 grid((NBND + 127) / 128, H / 128);
        gemm_k<<<grid, blk>>>(ALoadMsg{p_amsg, p_msgA, b2a, b2revb},
                              EpiMsg{p_inputs, p_msgB},
                              W_h, NBND, H, H);
    }

    // 3) depth iteration 2: msgB -> msgA
    aggregate_k<<<aggBlocks, blk>>>(p_msgB, a2b, p_amsg);
    {
        dim3 grid((NBND + 127) / 128, H / 128);
        gemm_k<<<grid, blk>>>(ALoadMsg{p_amsg, p_msgB, b2a, b2revb},
                              EpiMsg{p_inputs, p_msgA},
                              W_h, NBND, H, H);
    }

    // 4) final aggregation + atom readout
    aggregate_k<<<aggBlocks, blk>>>(p_msgA, a2b, p_amsg);
    {
        dim3 grid((NA + 127) / 128, H / 128);
        gemm_k<<<grid, blk>>>(ALoadConcat{f_atoms, p_amsg},
                              EpiBias{W_o_b, p_atomh, H},
                              W_o_w, NA, H, AF + H);
    }

    // 5) per-molecule mean + mol feature concat
    segmean_k<<<NM, blk>>>(p_atomh, atom2mol, mol_feat, p_molx);

    // 6) FFNN layer 1: h1 = relu(molx @ W1 + b1)
    {
        dim3 grid((NM + 127) / 128, F1 / 128);
        gemm_k<<<grid, blk>>>(ALoadDirect{p_molx, XDIM},
                              EpiBias{b1, p_h1, F1},
                              W1, NM, F1, XDIM);
    }

    // 7) FFNN layer 2: out = relu(h1 @ W2 + b2)
    {
        dim3 grid((NM + 127) / 128, F2 / 128);
        gemm_k<<<grid, blk>>>(ALoadDirect{p_h1, F1},
                              EpiBias{b2, out, F2},
                              W2, NM, F2, F1);
    }
}

// round 2
// speedup vs baseline: 1.1129x; 1.1129x over previous
#include <cuda_runtime.h>

#define NA 100000
#define NBND 200000
#define MAXNB 6
#define AF 133
#define BF 147
#define H 256
#define NM 4096
#define MF 200
#define XDIM (H + MF)   /* 456 */
#define F1 512
#define F2 256

typedef unsigned long long u64;

// ---------------- packed f32x2 helpers (SASS FFMA2 — PTX-only path) ---------
__device__ __forceinline__ u64 pack2(float lo, float hi) {
    u64 r;
    asm("mov.b64 %0, {%1, %2};" : "=l"(r) : "f"(lo), "f"(hi));
    return r;
}
__device__ __forceinline__ void unpack2(u64 v, float& lo, float& hi) {
    asm("mov.b64 {%0, %1}, %2;" : "=f"(lo), "=f"(hi) : "l"(v));
}
__device__ __forceinline__ u64 ffma2(u64 a, u64 b, u64 c) {
    u64 d;
    asm("fma.rn.f32x2 %0, %1, %2, %3;" : "=l"(d) : "l"(a), "l"(b), "l"(c));
    return d;
}

// ---------------- scratch (device globals; no allocations allowed) ----------
__device__ float g_inputs[NBND * H];   // pre-relu bond inputs
__device__ float g_msgA[NBND * H];
__device__ float g_msgB[NBND * H];
__device__ float g_amsg[NA * H];
__device__ float g_atomh[NA * H];
__device__ float g_molx[NM * XDIM];
__device__ float g_h1[NM * F1];

// ---------------- A-side loaders (prep(r) hoists per-row indices) -----------
struct ALoadDirect {
    const float* __restrict__ A;
    int ld;
    const float* row;
    __device__ __forceinline__ void prep(int r) { row = A + (long long)r * ld; }
    __device__ __forceinline__ float operator()(int k) const { return row[k]; }
};

// row r of A = a_message[b2a[r]] - message[b2revb[r]]   (K = 256)
struct ALoadMsg {
    const float* __restrict__ amsg;
    const float* __restrict__ msg;
    const int* __restrict__ b2a;
    const int* __restrict__ b2revb;
    const float* ra;
    const float* rb;
    __device__ __forceinline__ void prep(int r) {
        ra = amsg + (long long)b2a[r] * H;
        rb = msg + (long long)b2revb[r] * H;
    }
    __device__ __forceinline__ float operator()(int k) const { return ra[k] - rb[k]; }
};

// row r of A = concat(f_atoms[r] (133), a_message[r] (256))   (K = 389)
struct ALoadConcat {
    const float* __restrict__ fa;
    const float* __restrict__ amsg;
    const float* rf;
    const float* rm;
    __device__ __forceinline__ void prep(int r) {
        rf = fa + (long long)r * AF;
        rm = amsg + (long long)r * H;
    }
    __device__ __forceinline__ float operator()(int k) const {
        return (k < AF) ? rf[k] : rm[k - AF];
    }
};

// ---------------- epilogues -------------------------------------------------
struct EpiBond {            // store pre-relu inputs AND relu(message0)
    float* __restrict__ inputs;
    float* __restrict__ msg;
    __device__ __forceinline__ void operator()(int r, int n, float acc) const {
        long long o = (long long)r * H + n;
        inputs[o] = acc;
        msg[o] = fmaxf(acc, 0.f);
    }
};
struct EpiMsg {             // relu(inputs + acc)
    const float* __restrict__ inputs;
    float* __restrict__ out;
    __device__ __forceinline__ void operator()(int r, int n, float acc) const {
        long long o = (long long)r * H + n;
        out[o] = fmaxf(inputs[o] + acc, 0.f);
    }
};
struct EpiBias {            // relu(acc + bias[n]), arbitrary out ld
    const float* __restrict__ bias;
    float* __restrict__ out;
    int ld;
    __device__ __forceinline__ void operator()(int r, int n, float acc) const {
        out[(long long)r * ld + n] = fmaxf(acc + bias[n], 0.f);
    }
};

// ---------------- generic fp32 register-tiled GEMM with packed FFMA2 --------
// C[M,N] = A[M,K] @ B[K,N] (B row-major [K,N]), BM=BN=128, BK=16, 256 threads,
// 8x8 per-thread micro-tile held as 8x4 packed f32x2 accumulators.
template <class AL, class EP>
__global__ __launch_bounds__(256) void gemm_k(AL al, EP ep,
                                              const float* __restrict__ B,
                                              int M, int N, int K) {
    __shared__ float As[16][128];
    __shared__ float Bs[16][128];

    const int bm = blockIdx.x * 128;
    const int bn = blockIdx.y * 128;
    const int tid = threadIdx.x;
    const int arow = tid >> 1;          // 0..127
    const int akoff = (tid & 1) * 8;    // 0 or 8
    const int ty = tid >> 4;            // 0..15  -> rows ty*8..+8
    const int tx = tid & 15;            // 0..15  -> cols tx*8..+8

    u64 acc2[8][4];
#pragma unroll
    for (int i = 0; i < 8; i++)
#pragma unroll
        for (int j = 0; j < 4; j++) acc2[i][j] = 0ull;

    const int rA = bm + arow;
    const bool rAok = (rA < M);
    if (rAok) al.prep(rA);

    for (int k0 = 0; k0 < K; k0 += 16) {
        // load A tile (transposed into As[k][m])
#pragma unroll
        for (int j = 0; j < 8; j++) {
            int k = akoff + j;
            float v = (rAok && (k0 + k) < K) ? al(k0 + k) : 0.f;
            As[k][arow] = v;
        }
        // load B tile (coalesced along n)
#pragma unroll
        for (int j = 0; j < 8; j++) {
            int idx = tid + j * 256;
            int kk = idx >> 7;
            int n = idx & 127;
            float v = ((k0 + kk) < K) ? B[(long long)(k0 + kk) * N + bn + n] : 0.f;
            Bs[kk][n] = v;
        }
        __syncthreads();

#pragma unroll
        for (int kk = 0; kk < 16; kk++) {
            float4 a0 = *(const float4*)&As[kk][ty * 8];
            float4 a1 = *(const float4*)&As[kk][ty * 8 + 4];
            ulonglong2 bq0 = *(const ulonglong2*)&Bs[kk][tx * 8];
            ulonglong2 bq1 = *(const ulonglong2*)&Bs[kk][tx * 8 + 4];
            u64 bp[4] = {bq0.x, bq0.y, bq1.x, bq1.y};
            float af[8] = {a0.x, a0.y, a0.z, a0.w, a1.x, a1.y, a1.z, a1.w};
            u64 ad[8];
#pragma unroll
            for (int i = 0; i < 8; i++) ad[i] = pack2(af[i], af[i]);
#pragma unroll
            for (int i = 0; i < 8; i++)
#pragma unroll
                for (int j = 0; j < 4; j++)
                    acc2[i][j] = ffma2(ad[i], bp[j], acc2[i][j]);
        }
        __syncthreads();
    }

#pragma unroll
    for (int i = 0; i < 8; i++) {
        int r = bm + ty * 8 + i;
        if (r < M) {
#pragma unroll
            for (int j = 0; j < 4; j++) {
                float lo, hi;
                unpack2(acc2[i][j], lo, hi);
                ep(r, bn + tx * 8 + 2 * j, lo);
                ep(r, bn + tx * 8 + 2 * j + 1, hi);
            }
        }
    }
}

// ---------------- neighbor aggregation: amsg[a] = sum_j msg[a2b[a][j]] ------
__global__ __launch_bounds__(256) void aggregate_k(const float* __restrict__ msg,
                                                   const int* __restrict__ a2b,
                                                   float* __restrict__ amsg) {
    int i = blockIdx.x * blockDim.x + threadIdx.x;   // over NA * (H/4)
    if (i >= NA * (H / 4)) return;
    int a = i >> 6;
    int c = (i & 63) * 4;
    const int* nb = &a2b[a * MAXNB];
    float4 s = make_float4(0.f, 0.f, 0.f, 0.f);
#pragma unroll
    for (int j = 0; j < MAXNB; j++) {
        int b = nb[j];
        float4 v = *(const float4*)&msg[(long long)b * H + c];
        s.x += v.x; s.y += v.y; s.z += v.z; s.w += v.w;
    }
    *(float4*)&amsg[(long long)a * H + c] = s;
}

// ---------------- per-molecule mean (atom2mol sorted) + feature concat ------
__device__ __forceinline__ int lower_bound_i(const int* __restrict__ a, int n, int v) {
    int lo = 0, hi = n;
    while (lo < hi) {
        int mid = (lo + hi) >> 1;
        if (a[mid] < v) lo = mid + 1; else hi = mid;
    }
    return lo;
}

__global__ __launch_bounds__(256) void segmean_k(const float* __restrict__ atomh,
                                                 const int* __restrict__ atom2mol,
                                                 const float* __restrict__ molfeat,
                                                 float* __restrict__ molx) {
    int m = blockIdx.x;
    int tid = threadIdx.x;
    int start = lower_bound_i(atom2mol, NA, m);
    int end = lower_bound_i(atom2mol, NA, m + 1);
    int cnt = end - start;
    float inv = 1.f / (float)max(cnt, 1);
    float s = 0.f;
    for (int a = start; a < end; a++) s += atomh[(long long)a * H + tid];
    molx[(long long)m * XDIM + tid] = s * inv;
    if (tid < MF) molx[(long long)m * XDIM + H + tid] = molfeat[(long long)m * MF + tid];
}

// ---------------- launch ----------------------------------------------------
extern "C" void kernel_launch(void* const* d_in, const int* in_sizes, int n_in,
                              void* d_out, int out_size) {
    (void)in_sizes; (void)n_in; (void)out_size;
    const float* f_atoms   = (const float*)d_in[0];
    const float* f_bonds   = (const float*)d_in[1];
    const int*   a2b       = (const int*)d_in[2];
    const int*   b2a       = (const int*)d_in[3];
    const int*   b2revb    = (const int*)d_in[4];
    const int*   atom2mol  = (const int*)d_in[5];
    const float* mol_feat  = (const float*)d_in[6];
    const float* W_i       = (const float*)d_in[7];
    const float* W_h       = (const float*)d_in[8];
    const float* W_o_w     = (const float*)d_in[9];
    const float* W_o_b     = (const float*)d_in[10];
    const float* W1        = (const float*)d_in[11];
    const float* b1        = (const float*)d_in[12];
    const float* W2        = (const float*)d_in[13];
    const float* b2        = (const float*)d_in[14];
    float* out = (float*)d_out;

    float *p_inputs, *p_msgA, *p_msgB, *p_amsg, *p_atomh, *p_molx, *p_h1;
    cudaGetSymbolAddress((void**)&p_inputs, g_inputs);
    cudaGetSymbolAddress((void**)&p_msgA,   g_msgA);
    cudaGetSymbolAddress((void**)&p_msgB,   g_msgB);
    cudaGetSymbolAddress((void**)&p_amsg,   g_amsg);
    cudaGetSymbolAddress((void**)&p_atomh,  g_atomh);
    cudaGetSymbolAddress((void**)&p_molx,   g_molx);
    cudaGetSymbolAddress((void**)&p_h1,     g_h1);

    dim3 blk(256);

    // 1) inputs = f_bonds @ W_i ; msgA = relu(inputs)
    {
        dim3 grid((NBND + 127) / 128, H / 128);
        gemm_k<<<grid, blk>>>(ALoadDirect{f_bonds, BF},
                              EpiBond{p_inputs, p_msgA},
                              W_i, NBND, H, BF);
    }

    int aggBlocks = (NA * (H / 4) + 255) / 256;

    // 2) depth iteration 1: msgA -> msgB
    aggregate_k<<<aggBlocks, blk>>>(p_msgA, a2b, p_amsg);
    {
        dim3 grid((NBND + 127) / 128, H / 128);
        gemm_k<<<grid, blk>>>(ALoadMsg{p_amsg, p_msgA, b2a, b2revb},
                              EpiMsg{p_inputs, p_msgB},
                              W_h, NBND, H, H);
    }

    // 3) depth iteration 2: msgB -> msgA
    aggregate_k<<<aggBlocks, blk>>>(p_msgB, a2b, p_amsg);
    {
        dim3 grid((NBND + 127) / 128, H / 128);
        gemm_k<<<grid, blk>>>(ALoadMsg{p_amsg, p_msgB, b2a, b2revb},
                              EpiMsg{p_inputs, p_msgA},
                              W_h, NBND, H, H);
    }

    // 4) final aggregation + atom readout
    aggregate_k<<<aggBlocks, blk>>>(p_msgA, a2b, p_amsg);
    {
        dim3 grid((NA + 127) / 128, H / 128);
        gemm_k<<<grid, blk>>>(ALoadConcat{f_atoms, p_amsg},
                              EpiBias{W_o_b, p_atomh, H},
                              W_o_w, NA, H, AF + H);
    }

    // 5) per-molecule mean + mol feature concat
    segmean_k<<<NM, blk>>>(p_atomh, atom2mol, mol_feat, p_molx);

    // 6) FFNN layer 1: h1 = relu(molx @ W1 + b1)
    {
        dim3 grid((NM + 127) / 128, F1 / 128);
        gemm_k<<<grid, blk>>>(ALoadDirect{p_molx, XDIM},
                              EpiBias{b1, p_h1, F1},
                              W1, NM, F1, XDIM);
    }

    // 7) FFNN layer 2: out = relu(h1 @ W2 + b2)
    {
        dim3 grid((NM + 127) / 128, F2 / 128);
        gemm_k<<<grid, blk>>>(ALoadDirect{p_h1, F1},
                              EpiBias{b2, out, F2},
                              W2, NM, F2, F1);
    }
}

// round 8
// speedup vs baseline: 1.3569x; 1.2192x over previous
#include <cuda_runtime.h>
#include <cuda_bf16.h>
#include <cstdint>

#define NA 100000
#define NBND 200000
#define MAXNB 6
#define AF 133
#define BF 147
#define H 256
#define NM 4096
#define MF 200
#define XDIM (H + MF)   /* 456 */
#define F1 512
#define F2 256

// padded K (multiples of 64) for prepped transposed weights
#define KP_WI 192
#define KP_WH 256
#define KP_WO 448
#define KP_W1 512
#define KP_W2 512

// ==================== helpers ===============================================
__device__ __forceinline__ uint32_t smem_u32(const void* p) {
    uint32_t a;
    asm("{ .reg .u64 t; cvta.to.shared.u64 t, %1; cvt.u32.u64 %0, t; }" : "=r"(a) : "l"(p));
    return a;
}
#define SWZ(x) ((x) ^ (((x) >> 3) & 0x70))

__device__ __forceinline__ void ldsm_x4(uint32_t& r0, uint32_t& r1, uint32_t& r2, uint32_t& r3,
                                        uint32_t addr) {
    asm volatile("ldmatrix.sync.aligned.m8n8.x4.shared.b16 {%0,%1,%2,%3}, [%4];"
                 : "=r"(r0), "=r"(r1), "=r"(r2), "=r"(r3) : "r"(addr));
}
__device__ __forceinline__ void mma_bf16(float* d, const uint32_t* a, const uint32_t* b) {
    asm volatile("mma.sync.aligned.m16n8k16.row.col.f32.bf16.bf16.f32 "
                 "{%0,%1,%2,%3}, {%4,%5,%6,%7}, {%8,%9}, {%0,%1,%2,%3};"
                 : "+f"(d[0]), "+f"(d[1]), "+f"(d[2]), "+f"(d[3])
                 : "r"(a[0]), "r"(a[1]), "r"(a[2]), "r"(a[3]), "r"(b[0]), "r"(b[1]));
}

// ==================== scratch globals =======================================
__device__ float g_inputs[NBND * H];
__device__ float g_msgA[NBND * H];
__device__ float g_msgB[NBND * H];
__device__ float g_amsg[NA * H];
__device__ float g_atomh[NA * H];
__device__ float g_molx[NM * XDIM];
__device__ float g_h1[NM * F1];

// prepped transposed + padded + split weights, layout [N][Kpad] bf16
__device__ __nv_bfloat16 g_wi_h[H * KP_WI],  g_wi_l[H * KP_WI];
__device__ __nv_bfloat16 g_wh_h[H * KP_WH],  g_wh_l[H * KP_WH];
__device__ __nv_bfloat16 g_wo_h[H * KP_WO],  g_wo_l[H * KP_WO];
__device__ __nv_bfloat16 g_w1_h[F1 * KP_W1], g_w1_l[F1 * KP_W1];
__device__ __nv_bfloat16 g_w2_h[F2 * KP_W2], g_w2_l[F2 * KP_W2];

// ==================== weight prep: W[K][N] -> Wt_hi/lo[N][Kpad] =============
__global__ void prep_w(const float* __restrict__ W, __nv_bfloat16* __restrict__ hi,
                       __nv_bfloat16* __restrict__ lo, int K, int N, int Kpad) {
    int i = blockIdx.x * blockDim.x + threadIdx.x;
    if (i >= N * Kpad) return;
    int n = i / Kpad, k = i - n * Kpad;
    float x = (k < K) ? W[(long long)k * N + n] : 0.f;
    __nv_bfloat16 h = __float2bfloat16(x);
    hi[i] = h;
    lo[i] = __float2bfloat16(x - __bfloat162float(h));
}

// ==================== A-side loaders ========================================
struct TCDirect {
    const float* __restrict__ A; int ld; int K;
    __device__ __forceinline__ float4 load4(int r, int k) const {
        const float* row = A + (long long)r * ld;
        float4 v;
        v.x = (k     < K) ? row[k]     : 0.f;
        v.y = (k + 1 < K) ? row[k + 1] : 0.f;
        v.z = (k + 2 < K) ? row[k + 2] : 0.f;
        v.w = (k + 3 < K) ? row[k + 3] : 0.f;
        return v;
    }
};
struct TCMsg {   // A[r,k] = amsg[b2a[r]][k] - msg[b2revb[r]][k]  (K=256, aligned)
    const float* __restrict__ amsg; const float* __restrict__ msg;
    const int* __restrict__ b2a; const int* __restrict__ b2revb;
    __device__ __forceinline__ float4 load4(int r, int k) const {
        const float4 a = *(const float4*)(amsg + (long long)b2a[r] * H + k);
        const float4 b = *(const float4*)(msg + (long long)b2revb[r] * H + k);
        return make_float4(a.x - b.x, a.y - b.y, a.z - b.z, a.w - b.w);
    }
};
struct TCConcat { // A[r,:] = [f_atoms[r] (133) | amsg[r] (256)], K=389
    const float* __restrict__ fa; const float* __restrict__ amsg;
    __device__ __forceinline__ float4 load4(int r, int k) const {
        float o[4];
#pragma unroll
        for (int i = 0; i < 4; i++) {
            int kk = k + i; float v = 0.f;
            if (kk < AF) v = fa[(long long)r * AF + kk];
            else if (kk < AF + H) v = amsg[(long long)r * H + (kk - AF)];
            o[i] = v;
        }
        return make_float4(o[0], o[1], o[2], o[3]);
    }
};

// ==================== epilogues =============================================
struct EpiBond {
    float* __restrict__ inputs; float* __restrict__ msg;
    __device__ __forceinline__ void operator()(int r, int n, float acc) const {
        long long o = (long long)r * H + n;
        inputs[o] = acc; msg[o] = fmaxf(acc, 0.f);
    }
};
struct EpiMsg {
    const float* __restrict__ inputs; float* __restrict__ out;
    __device__ __forceinline__ void operator()(int r, int n, float acc) const {
        long long o = (long long)r * H + n;
        out[o] = fmaxf(inputs[o] + acc, 0.f);
    }
};
struct EpiBias {
    const float* __restrict__ bias; float* __restrict__ out; int ld;
    __device__ __forceinline__ void operator()(int r, int n, float acc) const {
        out[(long long)r * ld + n] = fmaxf(acc + bias[n], 0.f);
    }
};

// ==================== HMMA bf16 split GEMM ==================================
// C[M,N]: CTA tile 128x128, K-chunk 64. 8 warps = 4(m) x 2(n); warp tile 32x64.
// A fp32 via loader, split to bf16 hi/lo in SMEM; B prepped bf16 hi/lo [N][Kpad].
// D = Ah@Bh + Ah@Bl + Al@Bh with fp32 accumulators (3-term split, err ~2^-17).
// SMEM: A_hi 16K | A_lo 16K | B_hi 16K | B_lo 16K = 64 KB (dynamic).
#define OFF_AHI 0
#define OFF_ALO 16384
#define OFF_BHI 32768
#define OFF_BLO 49152
#define SM_TOTAL 65536

template <class AL, class EP>
__global__ __launch_bounds__(256) void tc_gemm(AL al, EP ep,
        const __nv_bfloat16* __restrict__ Bhi, const __nv_bfloat16* __restrict__ Blo,
        int M, int Kpad) {
    extern __shared__ char smem[];
    const uint32_t sb = smem_u32(smem);
    const int tid = threadIdx.x;
    const int wid = tid >> 5, lid = tid & 31;
    const int bm = blockIdx.x * 128;
    const int ncol = blockIdx.y * 128;

    const int wm = wid & 3;      // m quarter (32 rows)
    const int wn = wid >> 2;     // n half (64 cols)
    const int lj = lid >> 3;     // ldmatrix matrix index 0..3
    const int lr = lid & 7;

    float acc[2][8][4];
#pragma unroll
    for (int mf = 0; mf < 2; mf++)
#pragma unroll
        for (int nf = 0; nf < 8; nf++)
#pragma unroll
            for (int q = 0; q < 4; q++) acc[mf][nf][q] = 0.f;

    const int nch = Kpad / 64;
    for (int ch = 0; ch < nch; ch++) {
        const int k0 = ch * 64;
        __syncthreads();   // previous compute done before refill

        // ---- fill A tile: 128 rows x 64 cols, split to bf16 hi/lo ----------
        for (int t = tid; t < 128 * 16; t += 256) {
            int r = t >> 4;
            int c4 = (t & 15) << 2;
            float4 v = make_float4(0.f, 0.f, 0.f, 0.f);
            if (bm + r < M) v = al.load4(bm + r, k0 + c4);
            unsigned short h[4], l[4];
            float vv[4] = {v.x, v.y, v.z, v.w};
#pragma unroll
            for (int i = 0; i < 4; i++) {
                __nv_bfloat16 hb = __float2bfloat16(vv[i]);
                __nv_bfloat16 lb = __float2bfloat16(vv[i] - __bfloat162float(hb));
                h[i] = __bfloat16_as_ushort(hb);
                l[i] = __bfloat16_as_ushort(lb);
            }
            uint2 hv = make_uint2((uint32_t)h[0] | ((uint32_t)h[1] << 16),
                                  (uint32_t)h[2] | ((uint32_t)h[3] << 16));
            uint2 lv = make_uint2((uint32_t)l[0] | ((uint32_t)l[1] << 16),
                                  (uint32_t)l[2] | ((uint32_t)l[3] << 16));
            uint32_t sw = SWZ((uint32_t)(r * 128 + c4 * 2));
            *(uint2*)(smem + OFF_AHI + sw) = hv;
            *(uint2*)(smem + OFF_ALO + sw) = lv;
        }
        // ---- fill B tile: 128 n-rows x 64 k (uint4 = 8 bf16) ---------------
        {
            int n = tid >> 1;
            int half = tid & 1;
            const uint4* sh = (const uint4*)(Bhi + (long long)(ncol + n) * Kpad + k0);
            const uint4* sl = (const uint4*)(Blo + (long long)(ncol + n) * Kpad + k0);
#pragma unroll
            for (int j = 0; j < 4; j++) {
                int unit = half * 4 + j;
                uint32_t sw = SWZ((uint32_t)(n * 128 + unit * 16));
                *(uint4*)(smem + OFF_BHI + sw) = sh[unit];
                *(uint4*)(smem + OFF_BLO + sw) = sl[unit];
            }
        }
        __syncthreads();

        // ---- compute: 4 k-frags of 16 --------------------------------------
#pragma unroll
        for (int kf = 0; kf < 4; kf++) {
            uint32_t a_hi[2][4], a_lo[2][4];
#pragma unroll
            for (int mf = 0; mf < 2; mf++) {
                int row = wm * 32 + mf * 16 + lr + (lj & 1) * 8;
                uint32_t sw = SWZ((uint32_t)(row * 128 + kf * 32 + (lj >> 1) * 16));
                ldsm_x4(a_hi[mf][0], a_hi[mf][1], a_hi[mf][2], a_hi[mf][3], sb + OFF_AHI + sw);
                ldsm_x4(a_lo[mf][0], a_lo[mf][1], a_lo[mf][2], a_lo[mf][3], sb + OFF_ALO + sw);
            }
            uint32_t b_hi[8][2], b_lo[8][2];
#pragma unroll
            for (int np = 0; np < 4; np++) {
                int nrow = wn * 64 + np * 16 + lr + (lj & 1) * 8;
                uint32_t sw = SWZ((uint32_t)(nrow * 128 + kf * 32 + (lj >> 1) * 16));
                uint32_t r0, r1, r2, r3;
                ldsm_x4(r0, r1, r2, r3, sb + OFF_BHI + sw);
                b_hi[np * 2][0] = r0; b_hi[np * 2][1] = r2;
                b_hi[np * 2 + 1][0] = r1; b_hi[np * 2 + 1][1] = r3;
                ldsm_x4(r0, r1, r2, r3, sb + OFF_BLO + sw);
                b_lo[np * 2][0] = r0; b_lo[np * 2][1] = r2;
                b_lo[np * 2 + 1][0] = r1; b_lo[np * 2 + 1][1] = r3;
            }
#pragma unroll
            for (int mf = 0; mf < 2; mf++)
#pragma unroll
                for (int nf = 0; nf < 8; nf++) {
                    mma_bf16(acc[mf][nf], a_hi[mf], b_hi[nf]);
                    mma_bf16(acc[mf][nf], a_hi[mf], b_lo[nf]);
                    mma_bf16(acc[mf][nf], a_lo[mf], b_hi[nf]);
                }
        }
    }

    // ---- epilogue ----------------------------------------------------------
    const int er = bm + wm * 32 + (lid >> 2);
    const int ec = ncol + wn * 64 + (lid & 3) * 2;
#pragma unroll
    for (int mf = 0; mf < 2; mf++) {
        int r0 = er + mf * 16;
#pragma unroll
        for (int nf = 0; nf < 8; nf++) {
            int c = ec + nf * 8;
            if (r0 < M) {
                ep(r0, c, acc[mf][nf][0]);
                ep(r0, c + 1, acc[mf][nf][1]);
            }
            if (r0 + 8 < M) {
                ep(r0 + 8, c, acc[mf][nf][2]);
                ep(r0 + 8, c + 1, acc[mf][nf][3]);
            }
        }
    }
}

// ==================== aggregation + segmean =================================
__global__ __launch_bounds__(256) void aggregate_k(const float* __restrict__ msg,
                                                   const int* __restrict__ a2b,
                                                   float* __restrict__ amsg) {
    int i = blockIdx.x * blockDim.x + threadIdx.x;
    if (i >= NA * (H / 4)) return;
    int a = i >> 6;
    int c = (i & 63) * 4;
    const int* nb = &a2b[a * MAXNB];
    float4 s = make_float4(0.f, 0.f, 0.f, 0.f);
#pragma unroll
    for (int j = 0; j < MAXNB; j++) {
        float4 v = *(const float4*)&msg[(long long)nb[j] * H + c];
        s.x += v.x; s.y += v.y; s.z += v.z; s.w += v.w;
    }
    *(float4*)&amsg[(long long)a * H + c] = s;
}

__device__ __forceinline__ int lower_bound_i(const int* __restrict__ a, int n, int v) {
    int lo = 0, hi = n;
    while (lo < hi) { int mid = (lo + hi) >> 1; if (a[mid] < v) lo = mid + 1; else hi = mid; }
    return lo;
}
__global__ __launch_bounds__(256) void segmean_k(const float* __restrict__ atomh,
                                                 const int* __restrict__ atom2mol,
                                                 const float* __restrict__ molfeat,
                                                 float* __restrict__ molx) {
    int m = blockIdx.x;
    int tid = threadIdx.x;
    int start = lower_bound_i(atom2mol, NA, m);
    int end = lower_bound_i(atom2mol, NA, m + 1);
    float inv = 1.f / (float)max(end - start, 1);
    float s = 0.f;
    for (int a = start; a < end; a++) s += atomh[(long long)a * H + tid];
    molx[(long long)m * XDIM + tid] = s * inv;
    if (tid < MF) molx[(long long)m * XDIM + H + tid] = molfeat[(long long)m * MF + tid];
}

// ==================== launch ================================================
extern "C" void kernel_launch(void* const* d_in, const int* in_sizes, int n_in,
                              void* d_out, int out_size) {
    (void)in_sizes; (void)n_in; (void)out_size;
    const float* f_atoms  = (const float*)d_in[0];
    const float* f_bonds  = (const float*)d_in[1];
    const int*   a2b      = (const int*)d_in[2];
    const int*   b2a      = (const int*)d_in[3];
    const int*   b2revb   = (const int*)d_in[4];
    const int*   atom2mol = (const int*)d_in[5];
    const float* mol_feat = (const float*)d_in[6];
    const float* W_i      = (const float*)d_in[7];
    const float* W_h      = (const float*)d_in[8];
    const float* W_o_w    = (const float*)d_in[9];
    const float* W_o_b    = (const float*)d_in[10];
    const float* W1       = (const float*)d_in[11];
    const float* b1       = (const float*)d_in[12];
    const float* W2       = (const float*)d_in[13];
    const float* b2       = (const float*)d_in[14];
    float* out = (float*)d_out;

    float *p_inputs, *p_msgA, *p_msgB, *p_amsg, *p_atomh, *p_molx, *p_h1;
    cudaGetSymbolAddress((void**)&p_inputs, g_inputs);
    cudaGetSymbolAddress((void**)&p_msgA, g_msgA);
    cudaGetSymbolAddress((void**)&p_msgB, g_msgB);
    cudaGetSymbolAddress((void**)&p_amsg, g_amsg);
    cudaGetSymbolAddress((void**)&p_atomh, g_atomh);
    cudaGetSymbolAddress((void**)&p_molx, g_molx);
    cudaGetSymbolAddress((void**)&p_h1, g_h1);
    __nv_bfloat16 *wi_h, *wi_l, *wh_h, *wh_l, *wo_h, *wo_l, *w1_h, *w1_l, *w2_h, *w2_l;
    cudaGetSymbolAddress((void**)&wi_h, g_wi_h); cudaGetSymbolAddress((void**)&wi_l, g_wi_l);
    cudaGetSymbolAddress((void**)&wh_h, g_wh_h); cudaGetSymbolAddress((void**)&wh_l, g_wh_l);
    cudaGetSymbolAddress((void**)&wo_h, g_wo_h); cudaGetSymbolAddress((void**)&wo_l, g_wo_l);
    cudaGetSymbolAddress((void**)&w1_h, g_w1_h); cudaGetSymbolAddress((void**)&w1_l, g_w1_l);
    cudaGetSymbolAddress((void**)&w2_h, g_w2_h); cudaGetSymbolAddress((void**)&w2_l, g_w2_l);

    cudaFuncSetAttribute(tc_gemm<TCDirect, EpiBond>, cudaFuncAttributeMaxDynamicSharedMemorySize, SM_TOTAL);
    cudaFuncSetAttribute(tc_gemm<TCMsg, EpiMsg>,     cudaFuncAttributeMaxDynamicSharedMemorySize, SM_TOTAL);
    cudaFuncSetAttribute(tc_gemm<TCConcat, EpiBias>, cudaFuncAttributeMaxDynamicSharedMemorySize, SM_TOTAL);
    cudaFuncSetAttribute(tc_gemm<TCDirect, EpiBias>, cudaFuncAttributeMaxDynamicSharedMemorySize, SM_TOTAL);

    dim3 blk(256);

    // 0) prep weights (transpose + pad + bf16 hi/lo split)
    prep_w<<<(H * KP_WI + 255) / 256, blk>>>(W_i, wi_h, wi_l, BF, H, KP_WI);
    prep_w<<<(H * KP_WH + 255) / 256, blk>>>(W_h, wh_h, wh_l, H, H, KP_WH);
    prep_w<<<(H * KP_WO + 255) / 256, blk>>>(W_o_w, wo_h, wo_l, AF + H, H, KP_WO);
    prep_w<<<(F1 * KP_W1 + 255) / 256, blk>>>(W1, w1_h, w1_l, XDIM, F1, KP_W1);
    prep_w<<<(F2 * KP_W2 + 255) / 256, blk>>>(W2, w2_h, w2_l, F1, F2, KP_W2);

    const int MB_BND = (NBND + 127) / 128;   // 1563
    const int MB_A   = (NA + 127) / 128;     // 782
    const int aggBlocks = (NA * (H / 4) + 255) / 256;

    // 1) inputs = f_bonds @ W_i ; msgA = relu(inputs)
    tc_gemm<<<dim3(MB_BND, H / 128), blk, SM_TOTAL>>>(TCDirect{f_bonds, BF, BF},
        EpiBond{p_inputs, p_msgA}, wi_h, wi_l, NBND, KP_WI);

    // 2) iter 1: msgA -> msgB
    aggregate_k<<<aggBlocks, blk>>>(p_msgA, a2b, p_amsg);
    tc_gemm<<<dim3(MB_BND, H / 128), blk, SM_TOTAL>>>(TCMsg{p_amsg, p_msgA, b2a, b2revb},
        EpiMsg{p_inputs, p_msgB}, wh_h, wh_l, NBND, KP_WH);

    // 3) iter 2: msgB -> msgA
    aggregate_k<<<aggBlocks, blk>>>(p_msgB, a2b, p_amsg);
    tc_gemm<<<dim3(MB_BND, H / 128), blk, SM_TOTAL>>>(TCMsg{p_amsg, p_msgB, b2a, b2revb},
        EpiMsg{p_inputs, p_msgA}, wh_h, wh_l, NBND, KP_WH);

    // 4) final aggregation + atom readout
    aggregate_k<<<aggBlocks, blk>>>(p_msgA, a2b, p_amsg);
    tc_gemm<<<dim3(MB_A, H / 128), blk, SM_TOTAL>>>(TCConcat{f_atoms, p_amsg},
        EpiBias{W_o_b, p_atomh, H}, wo_h, wo_l, NA, KP_WO);

    // 5) per-molecule mean + feature concat
    segmean_k<<<NM, blk>>>(p_atomh, atom2mol, mol_feat, p_molx);

    // 6) FFNN layer 1: h1 = relu(molx @ W1 + b1)
    tc_gemm<<<dim3(NM / 128, F1 / 128), blk, SM_TOTAL>>>(TCDirect{p_molx, XDIM, XDIM},
        EpiBias{b1, p_h1, F1}, w1_h, w1_l, NM, KP_W1);

    // 7) FFNN layer 2: out = relu(h1 @ W2 + b2)
    tc_gemm<<<dim3(NM / 128, F2 / 128), blk, SM_TOTAL>>>(TCDirect{p_h1, F1, F1},
        EpiBias{b2, out, F2}, w2_h, w2_l, NM, KP_W2);
}

// round 9
// speedup vs baseline: 1.6794x; 1.2377x over previous
#include <cuda_runtime.h>
#include <cuda_bf16.h>
#include <cstdint>

#define NA 100000
#define NBND 200000
#define MAXNB 6
#define AF 133
#define BF 147
#define H 256
#define NM 4096
#define MF 200
#define XDIM (H + MF)   /* 456 */
#define F1 512
#define F2 256

// padded K (multiples of 64) for prepped transposed weights
#define KP_WI 192
#define KP_WH 256
#define KP_WO 448
#define KP_W1 512
#define KP_W2 512

// ==================== helpers ===============================================
__device__ __forceinline__ uint32_t smem_u32(const void* p) {
    uint32_t a;
    asm("{ .reg .u64 t; cvta.to.shared.u64 t, %1; cvt.u32.u64 %0, t; }" : "=r"(a) : "l"(p));
    return a;
}
#define SWZ(x) ((x) ^ (((x) >> 3) & 0x70))

__device__ __forceinline__ void ldsm_x4(uint32_t& r0, uint32_t& r1, uint32_t& r2, uint32_t& r3,
                                        uint32_t addr) {
    asm volatile("ldmatrix.sync.aligned.m8n8.x4.shared.b16 {%0,%1,%2,%3}, [%4];"
                 : "=r"(r0), "=r"(r1), "=r"(r2), "=r"(r3) : "r"(addr));
}
__device__ __forceinline__ void mma_bf16(float* d, const uint32_t* a, const uint32_t* b) {
    asm volatile("mma.sync.aligned.m16n8k16.row.col.f32.bf16.bf16.f32 "
                 "{%0,%1,%2,%3}, {%4,%5,%6,%7}, {%8,%9}, {%0,%1,%2,%3};"
                 : "+f"(d[0]), "+f"(d[1]), "+f"(d[2]), "+f"(d[3])
                 : "r"(a[0]), "r"(a[1]), "r"(a[2]), "r"(a[3]), "r"(b[0]), "r"(b[1]));
}
#define CP_ASYNC16(dst, src) \
    asm volatile("cp.async.cg.shared.global [%0], [%1], 16;" :: "r"(dst), "l"(src))
#define CP_COMMIT() asm volatile("cp.async.commit_group;" ::: "memory")
#define CP_WAIT0()  asm volatile("cp.async.wait_group 0;" ::: "memory")

// split one float4 into bf16 hi/lo packed pairs (12 instrs)
__device__ __forceinline__ void split4(float4 v, uint2& hv, uint2& lv) {
    __nv_bfloat162 h01 = __floats2bfloat162_rn(v.x, v.y);
    __nv_bfloat162 h23 = __floats2bfloat162_rn(v.z, v.w);
    uint32_t u01 = *(uint32_t*)&h01, u23 = *(uint32_t*)&h23;
    float hx = __uint_as_float(u01 << 16);
    float hy = __uint_as_float(u01 & 0xFFFF0000u);
    float hz = __uint_as_float(u23 << 16);
    float hw = __uint_as_float(u23 & 0xFFFF0000u);
    __nv_bfloat162 l01 = __floats2bfloat162_rn(v.x - hx, v.y - hy);
    __nv_bfloat162 l23 = __floats2bfloat162_rn(v.z - hz, v.w - hw);
    hv = make_uint2(u01, u23);
    lv = make_uint2(*(uint32_t*)&l01, *(uint32_t*)&l23);
}

// ==================== scratch globals =======================================
__device__ float g_inputs[NBND * H];
__device__ float g_msgA[NBND * H];
__device__ float g_msgB[NBND * H];
__device__ float g_amsg[NA * H];
__device__ float g_atomh[NA * H];
__device__ float g_molx[NM * XDIM];
__device__ float g_h1[NM * F1];

// prepped transposed + padded + split weights, layout [N][Kpad] bf16
__device__ __nv_bfloat16 g_wi_h[H * KP_WI],  g_wi_l[H * KP_WI];
__device__ __nv_bfloat16 g_wh_h[H * KP_WH],  g_wh_l[H * KP_WH];
__device__ __nv_bfloat16 g_wo_h[H * KP_WO],  g_wo_l[H * KP_WO];
__device__ __nv_bfloat16 g_w1_h[F1 * KP_W1], g_w1_l[F1 * KP_W1];
__device__ __nv_bfloat16 g_w2_h[F2 * KP_W2], g_w2_l[F2 * KP_W2];

// ==================== weight prep: W[K][N] -> Wt_hi/lo[N][Kpad] =============
__global__ void prep_w(const float* __restrict__ W, __nv_bfloat16* __restrict__ hi,
                       __nv_bfloat16* __restrict__ lo, int K, int N, int Kpad) {
    int i = blockIdx.x * blockDim.x + threadIdx.x;
    if (i >= N * Kpad) return;
    int n = i / Kpad, k = i - n * Kpad;
    float x = (k < K) ? W[(long long)k * N + n] : 0.f;
    __nv_bfloat16 h = __float2bfloat16(x);
    hi[i] = h;
    lo[i] = __float2bfloat16(x - __bfloat162float(h));
}

// ==================== A-side loaders ========================================
struct TCDirect {
    const float* __restrict__ A; int ld; int K;
    __device__ __forceinline__ float4 load4(int r, int k) const {
        const float* row = A + (long long)r * ld;
        float4 v;
        v.x = (k     < K) ? row[k]     : 0.f;
        v.y = (k + 1 < K) ? row[k + 1] : 0.f;
        v.z = (k + 2 < K) ? row[k + 2] : 0.f;
        v.w = (k + 3 < K) ? row[k + 3] : 0.f;
        return v;
    }
};
struct TCMsg {   // A[r,k] = amsg[b2a[r]][k] - msg[b2revb[r]][k]  (K=256, aligned)
    const float* __restrict__ amsg; const float* __restrict__ msg;
    const int* __restrict__ b2a; const int* __restrict__ b2revb;
    __device__ __forceinline__ float4 load4(int r, int k) const {
        const float4 a = *(const float4*)(amsg + (long long)b2a[r] * H + k);
        const float4 b = *(const float4*)(msg + (long long)b2revb[r] * H + k);
        return make_float4(a.x - b.x, a.y - b.y, a.z - b.z, a.w - b.w);
    }
};
struct TCConcat { // A[r,:] = [f_atoms[r] (133) | amsg[r] (256)], K=389
    const float* __restrict__ fa; const float* __restrict__ amsg;
    __device__ __forceinline__ float4 load4(int r, int k) const {
        float o[4];
#pragma unroll
        for (int i = 0; i < 4; i++) {
            int kk = k + i; float v = 0.f;
            if (kk < AF) v = fa[(long long)r * AF + kk];
            else if (kk < AF + H) v = amsg[(long long)r * H + (kk - AF)];
            o[i] = v;
        }
        return make_float4(o[0], o[1], o[2], o[3]);
    }
};

// ==================== epilogues =============================================
struct EpiBond {
    float* __restrict__ inputs; float* __restrict__ msg;
    __device__ __forceinline__ void operator()(int r, int n, float acc) const {
        long long o = (long long)r * H + n;
        inputs[o] = acc; msg[o] = fmaxf(acc, 0.f);
    }
};
struct EpiMsg {
    const float* __restrict__ inputs; float* __restrict__ out;
    __device__ __forceinline__ void operator()(int r, int n, float acc) const {
        long long o = (long long)r * H + n;
        out[o] = fmaxf(inputs[o] + acc, 0.f);
    }
};
struct EpiBias {
    const float* __restrict__ bias; float* __restrict__ out; int ld;
    __device__ __forceinline__ void operator()(int r, int n, float acc) const {
        out[(long long)r * ld + n] = fmaxf(acc + bias[n], 0.f);
    }
};

// ==================== HMMA bf16 split GEMM, BN=256, 2-stage pipeline ========
// CTA tile 128x256, K-chunk 64. 8 warps = 4(m) x 2(n); warp tile 32x128.
// D = Ah@Bh + Ah@Bl + Al@Bh, fp32 accumulators (err ~2^-17).
// SMEM per stage: A_hi 16K | A_lo 16K | B_hi 32K | B_lo 32K = 96 KB; 2 stages.
#define ST_AHI 0
#define ST_ALO 16384
#define ST_BHI 32768
#define ST_BLO 65536
#define ST_SIZE 98304
#define SM_TOTAL (2 * ST_SIZE)

template <class AL, class EP>
__global__ __launch_bounds__(256, 1) void tc_gemm(AL al, EP ep,
        const __nv_bfloat16* __restrict__ Bhi, const __nv_bfloat16* __restrict__ Blo,
        int M, int Kpad) {
    extern __shared__ char smem[];
    const uint32_t sb = smem_u32(smem);
    const int tid = threadIdx.x;
    const int wid = tid >> 5, lid = tid & 31;
    const int bm = blockIdx.x * 128;
    const int ncol = blockIdx.y * 256;

    const int wm = wid & 3;      // m quarter (32 rows)
    const int wn = wid >> 2;     // n half (128 cols)
    const int lj = lid >> 3;     // ldmatrix matrix index 0..3
    const int lr = lid & 7;

    float acc[2][16][4];
#pragma unroll
    for (int mf = 0; mf < 2; mf++)
#pragma unroll
        for (int nf = 0; nf < 16; nf++)
#pragma unroll
            for (int q = 0; q < 4; q++) acc[mf][nf][q] = 0.f;

    const int nch = Kpad / 64;

    auto fill = [&](int stg, int ch) {
        const int k0 = ch * 64;
        char* base = smem + stg * ST_SIZE;
        // A tile: 128 rows x 64 cols fp32 -> bf16 hi/lo
#pragma unroll
        for (int it = 0; it < 8; it++) {
            int t = tid + it * 256;
            int r = t >> 4;
            int c4 = (t & 15) << 2;
            float4 v = make_float4(0.f, 0.f, 0.f, 0.f);
            if (bm + r < M) v = al.load4(bm + r, k0 + c4);
            uint2 hv, lv;
            split4(v, hv, lv);
            uint32_t sw = SWZ((uint32_t)(r * 128 + c4 * 2));
            *(uint2*)(base + ST_AHI + sw) = hv;
            *(uint2*)(base + ST_ALO + sw) = lv;
        }
        // B tile: 256 n-rows x 64 k, raw bf16 copies via cp.async
        {
            int n = tid;
            const char* sh = (const char*)(Bhi + (long long)(ncol + n) * Kpad + k0);
            const char* sl = (const char*)(Blo + (long long)(ncol + n) * Kpad + k0);
            uint32_t rowoff = (uint32_t)(n * 128);
            uint32_t bh = sb + stg * ST_SIZE + ST_BHI;
            uint32_t bl = sb + stg * ST_SIZE + ST_BLO;
#pragma unroll
            for (int j = 0; j < 8; j++) {
                uint32_t sw = SWZ(rowoff + j * 16);
                CP_ASYNC16(bh + sw, sh + j * 16);
                CP_ASYNC16(bl + sw, sl + j * 16);
            }
        }
    };

    auto compute = [&](int stg) {
        const uint32_t ba = sb + stg * ST_SIZE;
#pragma unroll
        for (int kf = 0; kf < 4; kf++) {
            uint32_t a_hi[2][4], a_lo[2][4];
#pragma unroll
            for (int mf = 0; mf < 2; mf++) {
                int row = wm * 32 + mf * 16 + lr + (lj & 1) * 8;
                uint32_t sw = SWZ((uint32_t)(row * 128 + kf * 32 + (lj >> 1) * 16));
                ldsm_x4(a_hi[mf][0], a_hi[mf][1], a_hi[mf][2], a_hi[mf][3], ba + ST_AHI + sw);
                ldsm_x4(a_lo[mf][0], a_lo[mf][1], a_lo[mf][2], a_lo[mf][3], ba + ST_ALO + sw);
            }
#pragma unroll
            for (int np = 0; np < 8; np++) {
                int nrow = wn * 128 + np * 16 + lr + (lj & 1) * 8;
                uint32_t sw = SWZ((uint32_t)(nrow * 128 + kf * 32 + (lj >> 1) * 16));
                uint32_t bh[2][2], bl[2][2];
                uint32_t r0, r1, r2, r3;
                ldsm_x4(r0, r1, r2, r3, ba + ST_BHI + sw);
                bh[0][0] = r0; bh[0][1] = r2; bh[1][0] = r1; bh[1][1] = r3;
                ldsm_x4(r0, r1, r2, r3, ba + ST_BLO + sw);
                bl[0][0] = r0; bl[0][1] = r2; bl[1][0] = r1; bl[1][1] = r3;
#pragma unroll
                for (int mf = 0; mf < 2; mf++)
#pragma unroll
                    for (int sub = 0; sub < 2; sub++) {
                        int nf = np * 2 + sub;
                        mma_bf16(acc[mf][nf], a_hi[mf], bh[sub]);
                        mma_bf16(acc[mf][nf], a_hi[mf], bl[sub]);
                        mma_bf16(acc[mf][nf], a_lo[mf], bh[sub]);
                    }
            }
        }
    };

    fill(0, 0);
    CP_COMMIT();
    for (int ch = 0; ch < nch; ch++) {
        int cur = ch & 1;
        CP_WAIT0();
        __syncthreads();
        if (ch + 1 < nch) { fill(cur ^ 1, ch + 1); CP_COMMIT(); }
        compute(cur);
    }

    // ---- epilogue ----------------------------------------------------------
    const int er = bm + wm * 32 + (lid >> 2);
    const int ec = ncol + wn * 128 + (lid & 3) * 2;
#pragma unroll
    for (int mf = 0; mf < 2; mf++) {
        int r0 = er + mf * 16;
#pragma unroll
        for (int nf = 0; nf < 16; nf++) {
            int c = ec + nf * 8;
            if (r0 < M) {
                ep(r0, c, acc[mf][nf][0]);
                ep(r0, c + 1, acc[mf][nf][1]);
            }
            if (r0 + 8 < M) {
                ep(r0 + 8, c, acc[mf][nf][2]);
                ep(r0 + 8, c + 1, acc[mf][nf][3]);
            }
        }
    }
}

// ==================== aggregation + segmean =================================
__global__ __launch_bounds__(256) void aggregate_k(const float* __restrict__ msg,
                                                   const int* __restrict__ a2b,
                                                   float* __restrict__ amsg) {
    int i = blockIdx.x * blockDim.x + threadIdx.x;
    if (i >= NA * (H / 4)) return;
    int a = i >> 6;
    int c = (i & 63) * 4;
    const int* nb = &a2b[a * MAXNB];
    float4 s = make_float4(0.f, 0.f, 0.f, 0.f);
#pragma unroll
    for (int j = 0; j < MAXNB; j++) {
        float4 v = *(const float4*)&msg[(long long)nb[j] * H + c];
        s.x += v.x; s.y += v.y; s.z += v.z; s.w += v.w;
    }
    *(float4*)&amsg[(long long)a * H + c] = s;
}

__device__ __forceinline__ int lower_bound_i(const int* __restrict__ a, int n, int v) {
    int lo = 0, hi = n;
    while (lo < hi) { int mid = (lo + hi) >> 1; if (a[mid] < v) lo = mid + 1; else hi = mid; }
    return lo;
}
__global__ __launch_bounds__(256) void segmean_k(const float* __restrict__ atomh,
                                                 const int* __restrict__ atom2mol,
                                                 const float* __restrict__ molfeat,
                                                 float* __restrict__ molx) {
    int m = blockIdx.x;
    int tid = threadIdx.x;
    int start = lower_bound_i(atom2mol, NA, m);
    int end = lower_bound_i(atom2mol, NA, m + 1);
    float inv = 1.f / (float)max(end - start, 1);
    float s = 0.f;
    for (int a = start; a < end; a++) s += atomh[(long long)a * H + tid];
    molx[(long long)m * XDIM + tid] = s * inv;
    if (tid < MF) molx[(long long)m * XDIM + H + tid] = molfeat[(long long)m * MF + tid];
}

// ==================== launch ================================================
extern "C" void kernel_launch(void* const* d_in, const int* in_sizes, int n_in,
                              void* d_out, int out_size) {
    (void)in_sizes; (void)n_in; (void)out_size;
    const float* f_atoms  = (const float*)d_in[0];
    const float* f_bonds  = (const float*)d_in[1];
    const int*   a2b      = (const int*)d_in[2];
    const int*   b2a      = (const int*)d_in[3];
    const int*   b2revb   = (const int*)d_in[4];
    const int*   atom2mol = (const int*)d_in[5];
    const float* mol_feat = (const float*)d_in[6];
    const float* W_i      = (const float*)d_in[7];
    const float* W_h      = (const float*)d_in[8];
    const float* W_o_w    = (const float*)d_in[9];
    const float* W_o_b    = (const float*)d_in[10];
    const float* W1       = (const float*)d_in[11];
    const float* b1       = (const float*)d_in[12];
    const float* W2       = (const float*)d_in[13];
    const float* b2       = (const float*)d_in[14];
    float* out = (float*)d_out;

    float *p_inputs, *p_msgA, *p_msgB, *p_amsg, *p_atomh, *p_molx, *p_h1;
    cudaGetSymbolAddress((void**)&p_inputs, g_inputs);
    cudaGetSymbolAddress((void**)&p_msgA, g_msgA);
    cudaGetSymbolAddress((void**)&p_msgB, g_msgB);
    cudaGetSymbolAddress((void**)&p_amsg, g_amsg);
    cudaGetSymbolAddress((void**)&p_atomh, g_atomh);
    cudaGetSymbolAddress((void**)&p_molx, g_molx);
    cudaGetSymbolAddress((void**)&p_h1, g_h1);
    __nv_bfloat16 *wi_h, *wi_l, *wh_h, *wh_l, *wo_h, *wo_l, *w1_h, *w1_l, *w2_h, *w2_l;
    cudaGetSymbolAddress((void**)&wi_h, g_wi_h); cudaGetSymbolAddress((void**)&wi_l, g_wi_l);
    cudaGetSymbolAddress((void**)&wh_h, g_wh_h); cudaGetSymbolAddress((void**)&wh_l, g_wh_l);
    cudaGetSymbolAddress((void**)&wo_h, g_wo_h); cudaGetSymbolAddress((void**)&wo_l, g_wo_l);
    cudaGetSymbolAddress((void**)&w1_h, g_w1_h); cudaGetSymbolAddress((void**)&w1_l, g_w1_l);
    cudaGetSymbolAddress((void**)&w2_h, g_w2_h); cudaGetSymbolAddress((void**)&w2_l, g_w2_l);

    cudaFuncSetAttribute(tc_gemm<TCDirect, EpiBond>, cudaFuncAttributeMaxDynamicSharedMemorySize, SM_TOTAL);
    cudaFuncSetAttribute(tc_gemm<TCMsg, EpiMsg>,     cudaFuncAttributeMaxDynamicSharedMemorySize, SM_TOTAL);
    cudaFuncSetAttribute(tc_gemm<TCConcat, EpiBias>, cudaFuncAttributeMaxDynamicSharedMemorySize, SM_TOTAL);
    cudaFuncSetAttribute(tc_gemm<TCDirect, EpiBias>, cudaFuncAttributeMaxDynamicSharedMemorySize, SM_TOTAL);

    dim3 blk(256);

    // 0) prep weights (transpose + pad + bf16 hi/lo split)
    prep_w<<<(H * KP_WI + 255) / 256, blk>>>(W_i, wi_h, wi_l, BF, H, KP_WI);
    prep_w<<<(H * KP_WH + 255) / 256, blk>>>(W_h, wh_h, wh_l, H, H, KP_WH);
    prep_w<<<(H * KP_WO + 255) / 256, blk>>>(W_o_w, wo_h, wo_l, AF + H, H, KP_WO);
    prep_w<<<(F1 * KP_W1 + 255) / 256, blk>>>(W1, w1_h, w1_l, XDIM, F1, KP_W1);
    prep_w<<<(F2 * KP_W2 + 255) / 256, blk>>>(W2, w2_h, w2_l, F1, F2, KP_W2);

    const int MB_BND = (NBND + 127) / 128;   // 1563
    const int MB_A   = (NA + 127) / 128;     // 782
    const int aggBlocks = (NA * (H / 4) + 255) / 256;

    // 1) inputs = f_bonds @ W_i ; msgA = relu(inputs)
    tc_gemm<<<dim3(MB_BND, 1), blk, SM_TOTAL>>>(TCDirect{f_bonds, BF, BF},
        EpiBond{p_inputs, p_msgA}, wi_h, wi_l, NBND, KP_WI);

    // 2) iter 1: msgA -> msgB
    aggregate_k<<<aggBlocks, blk>>>(p_msgA, a2b, p_amsg);
    tc_gemm<<<dim3(MB_BND, 1), blk, SM_TOTAL>>>(TCMsg{p_amsg, p_msgA, b2a, b2revb},
        EpiMsg{p_inputs, p_msgB}, wh_h, wh_l, NBND, KP_WH);

    // 3) iter 2: msgB -> msgA
    aggregate_k<<<aggBlocks, blk>>>(p_msgB, a2b, p_amsg);
    tc_gemm<<<dim3(MB_BND, 1), blk, SM_TOTAL>>>(TCMsg{p_amsg, p_msgB, b2a, b2revb},
        EpiMsg{p_inputs, p_msgA}, wh_h, wh_l, NBND, KP_WH);

    // 4) final aggregation + atom readout
    aggregate_k<<<aggBlocks, blk>>>(p_msgA, a2b, p_amsg);
    tc_gemm<<<dim3(MB_A, 1), blk, SM_TOTAL>>>(TCConcat{f_atoms, p_amsg},
        EpiBias{W_o_b, p_atomh, H}, wo_h, wo_l, NA, KP_WO);

    // 5) per-molecule mean + feature concat
    segmean_k<<<NM, blk>>>(p_atomh, atom2mol, mol_feat, p_molx);

    // 6) FFNN layer 1: h1 = relu(molx @ W1 + b1)
    tc_gemm<<<dim3(NM / 128, F1 / 256), blk, SM_TOTAL>>>(TCDirect{p_molx, XDIM, XDIM},
        EpiBias{b1, p_h1, F1}, w1_h, w1_l, NM, KP_W1);

    // 7) FFNN layer 2: out = relu(h1 @ W2 + b2)
    tc_gemm<<<dim3(NM / 128, F2 / 256), blk, SM_TOTAL>>>(TCDirect{p_h1, F1, F1},
        EpiBias{b2, out, F2}, w2_h, w2_l, NM, KP_W2);
}

// round 11
// speedup vs baseline: 2.2186x; 1.3211x over previous
#include <cuda_runtime.h>
#include <cuda_bf16.h>
#include <cstdint>

#define NA 100000
#define NBND 200000
#define MAXNB 6
#define AF 133
#define BF 147
#define H 256
#define NM 4096
#define MF 200
#define XDIM (H + MF)   /* 456 */
#define F1 512
#define F2 256

// padded K (multiples of 64) for prepped transposed weights
#define KP_WI 192
#define KP_WH 256
#define KP_WO 448
#define KP_W1 512
#define KP_W2 512

// ==================== helpers ===============================================
__device__ __forceinline__ uint32_t smem_u32(const void* p) {
    uint32_t a;
    asm("{ .reg .u64 t; cvta.to.shared.u64 t, %1; cvt.u32.u64 %0, t; }" : "=r"(a) : "l"(p));
    return a;
}
#define SWZ(x) ((x) ^ (((x) >> 3) & 0x70))

__device__ __forceinline__ void ldsm_x4(uint32_t& r0, uint32_t& r1, uint32_t& r2, uint32_t& r3,
                                        uint32_t addr) {
    asm volatile("ldmatrix.sync.aligned.m8n8.x4.shared.b16 {%0,%1,%2,%3}, [%4];"
                 : "=r"(r0), "=r"(r1), "=r"(r2), "=r"(r3) : "r"(addr));
}
__device__ __forceinline__ void mma_bf16(float* d, const uint32_t* a, const uint32_t* b) {
    asm volatile("mma.sync.aligned.m16n8k16.row.col.f32.bf16.bf16.f32 "
                 "{%0,%1,%2,%3}, {%4,%5,%6,%7}, {%8,%9}, {%0,%1,%2,%3};"
                 : "+f"(d[0]), "+f"(d[1]), "+f"(d[2]), "+f"(d[3])
                 : "r"(a[0]), "r"(a[1]), "r"(a[2]), "r"(a[3]), "r"(b[0]), "r"(b[1]));
}
#define CP_ASYNC16(dst, src) \
    asm volatile("cp.async.cg.shared.global [%0], [%1], 16;" :: "r"(dst), "l"(src))
#define CP_COMMIT() asm volatile("cp.async.commit_group;" ::: "memory")
#define CP_WAIT0()  asm volatile("cp.async.wait_group 0;" ::: "memory")

// split one float4 into bf16 hi/lo packed pairs
__device__ __forceinline__ void split4(float4 v, uint2& hv, uint2& lv) {
    __nv_bfloat162 h01 = __floats2bfloat162_rn(v.x, v.y);
    __nv_bfloat162 h23 = __floats2bfloat162_rn(v.z, v.w);
    uint32_t u01 = *(uint32_t*)&h01, u23 = *(uint32_t*)&h23;
    float hx = __uint_as_float(u01 << 16);
    float hy = __uint_as_float(u01 & 0xFFFF0000u);
    float hz = __uint_as_float(u23 << 16);
    float hw = __uint_as_float(u23 & 0xFFFF0000u);
    __nv_bfloat162 l01 = __floats2bfloat162_rn(v.x - hx, v.y - hy);
    __nv_bfloat162 l23 = __floats2bfloat162_rn(v.z - hz, v.w - hw);
    hv = make_uint2(u01, u23);
    lv = make_uint2(*(uint32_t*)&l01, *(uint32_t*)&l23);
}

// ==================== scratch globals =======================================
__device__ float g_inputs[NBND * H];
__device__ float g_msgA[NBND * H];   // current message
__device__ float g_P[NBND * H];      // P = msg @ W_h
__device__ float g_amsg[NA * H];
__device__ float g_atomh[NA * H];
__device__ float g_molx[NM * XDIM];
__device__ float g_h1[NM * F1];

// prepped transposed + padded + split weights, layout [N][Kpad] bf16
__device__ __nv_bfloat16 g_wi_h[H * KP_WI],  g_wi_l[H * KP_WI];
__device__ __nv_bfloat16 g_wh_h[H * KP_WH],  g_wh_l[H * KP_WH];
__device__ __nv_bfloat16 g_wo_h[H * KP_WO],  g_wo_l[H * KP_WO];
__device__ __nv_bfloat16 g_w1_h[F1 * KP_W1], g_w1_l[F1 * KP_W1];
__device__ __nv_bfloat16 g_w2_h[F2 * KP_W2], g_w2_l[F2 * KP_W2];

// ==================== weight prep: W[K][N] -> Wt_hi/lo[N][Kpad] =============
__global__ void prep_w(const float* __restrict__ W, __nv_bfloat16* __restrict__ hi,
                       __nv_bfloat16* __restrict__ lo, int K, int N, int Kpad) {
    int i = blockIdx.x * blockDim.x + threadIdx.x;
    if (i >= N * Kpad) return;
    int n = i / Kpad, k = i - n * Kpad;
    float x = (k < K) ? W[(long long)k * N + n] : 0.f;
    __nv_bfloat16 h = __float2bfloat16(x);
    hi[i] = h;
    lo[i] = __float2bfloat16(x - __bfloat162float(h));
}

// ==================== A-side loaders ========================================
struct TCDirect {
    const float* __restrict__ A; int ld; int K;
    __device__ __forceinline__ float4 load4(int r, int k) const {
        const float* row = A + (long long)r * ld;
        float4 v;
        v.x = (k     < K) ? row[k]     : 0.f;
        v.y = (k + 1 < K) ? row[k + 1] : 0.f;
        v.z = (k + 2 < K) ? row[k + 2] : 0.f;
        v.w = (k + 3 < K) ? row[k + 3] : 0.f;
        return v;
    }
};
struct TCConcat { // A[r,:] = [f_atoms[r] (133) | amsg[r] (256)], K=389
    const float* __restrict__ fa; const float* __restrict__ amsg;
    __device__ __forceinline__ float4 load4(int r, int k) const {
        float o[4];
#pragma unroll
        for (int i = 0; i < 4; i++) {
            int kk = k + i; float v = 0.f;
            if (kk < AF) v = fa[(long long)r * AF + kk];
            else if (kk < AF + H) v = amsg[(long long)r * H + (kk - AF)];
            o[i] = v;
        }
        return make_float4(o[0], o[1], o[2], o[3]);
    }
};

// ==================== epilogues =============================================
struct EpiBond {
    float* __restrict__ inputs; float* __restrict__ msg;
    __device__ __forceinline__ void operator()(int r, int n, float acc) const {
        long long o = (long long)r * H + n;
        inputs[o] = acc; msg[o] = fmaxf(acc, 0.f);
    }
};
struct EpiStore {
    float* __restrict__ out;
    __device__ __forceinline__ void operator()(int r, int n, float acc) const {
        out[(long long)r * H + n] = acc;
    }
};
struct EpiBias {
    const float* __restrict__ bias; float* __restrict__ out; int ld;
    __device__ __forceinline__ void operator()(int r, int n, float acc) const {
        out[(long long)r * ld + n] = fmaxf(acc + bias[n], 0.f);
    }
};

// ==================== HMMA bf16 split GEMM, BM=64 BN=128, 2-stage ===========
// CTA tile 64x128, K-chunk 64. 8 warps = 2(m) x 4(n); warp tile 32x32.
// D = Ah@Bh + Ah@Bl + Al@Bh, fp32 accumulators (err ~2^-17).
// SMEM/stage: A_hi 8K | A_lo 8K | B_hi 16K | B_lo 16K = 48 KB; 2 stages = 96 KB
// -> 2 CTAs/SM (4 warps/SMSP) for latency hiding.
#define ST_AHI 0
#define ST_ALO 8192
#define ST_BHI 16384
#define ST_BLO 32768
#define ST_SIZE 49152
#define SM_TOTAL (2 * ST_SIZE)

template <class AL, class EP>
__global__ __launch_bounds__(256, 2) void tc_gemm(AL al, EP ep,
        const __nv_bfloat16* __restrict__ Bhi, const __nv_bfloat16* __restrict__ Blo,
        int M, int Kpad) {
    extern __shared__ char smem[];
    const uint32_t sb = smem_u32(smem);
    const int tid = threadIdx.x;
    const int wid = tid >> 5, lid = tid & 31;
    const int bm = blockIdx.x * 64;
    const int ncol = blockIdx.y * 128;

    const int wm = wid & 1;      // m half (32 rows)
    const int wn = wid >> 1;     // n quarter (32 cols)
    const int lj = lid >> 3;     // ldmatrix matrix index 0..3
    const int lr = lid & 7;

    float acc[2][4][4];
#pragma unroll
    for (int mf = 0; mf < 2; mf++)
#pragma unroll
        for (int nf = 0; nf < 4; nf++)
#pragma unroll
            for (int q = 0; q < 4; q++) acc[mf][nf][q] = 0.f;

    const int nch = Kpad / 64;

    auto fill = [&](int stg, int ch) {
        const int k0 = ch * 64;
        char* base = smem + stg * ST_SIZE;
        // A tile: 64 rows x 64 cols fp32 -> bf16 hi/lo  (1024 float4, 4/thread)
#pragma unroll
        for (int it = 0; it < 4; it++) {
            int t = tid + it * 256;
            int r = t >> 4;
            int c4 = (t & 15) << 2;
            float4 v = make_float4(0.f, 0.f, 0.f, 0.f);
            if (bm + r < M) v = al.load4(bm + r, k0 + c4);
            uint2 hv, lv;
            split4(v, hv, lv);
            uint32_t sw = SWZ((uint32_t)(r * 128 + c4 * 2));
            *(uint2*)(base + ST_AHI + sw) = hv;
            *(uint2*)(base + ST_ALO + sw) = lv;
        }
        // B tile: 128 n-rows x 64 k, raw bf16 via cp.async (2 threads/row)
        {
            int n = tid >> 1;
            int half = tid & 1;
            const char* sh = (const char*)(Bhi + (long long)(ncol + n) * Kpad + k0);
            const char* sl = (const char*)(Blo + (long long)(ncol + n) * Kpad + k0);
            uint32_t rowoff = (uint32_t)(n * 128);
            uint32_t bh = sb + stg * ST_SIZE + ST_BHI;
            uint32_t bl = sb + stg * ST_SIZE + ST_BLO;
#pragma unroll
            for (int j = 0; j < 4; j++) {
                int unit = half * 4 + j;
                uint32_t sw = SWZ(rowoff + unit * 16);
                CP_ASYNC16(bh + sw, sh + unit * 16);
                CP_ASYNC16(bl + sw, sl + unit * 16);
            }
        }
    };

    auto compute = [&](int stg) {
        const uint32_t ba = sb + stg * ST_SIZE;
#pragma unroll
        for (int kf = 0; kf < 4; kf++) {
            uint32_t a_hi[2][4], a_lo[2][4];
#pragma unroll
            for (int mf = 0; mf < 2; mf++) {
                int row = wm * 32 + mf * 16 + lr + (lj & 1) * 8;
                uint32_t sw = SWZ((uint32_t)(row * 128 + kf * 32 + (lj >> 1) * 16));
                ldsm_x4(a_hi[mf][0], a_hi[mf][1], a_hi[mf][2], a_hi[mf][3], ba + ST_AHI + sw);
                ldsm_x4(a_lo[mf][0], a_lo[mf][1], a_lo[mf][2], a_lo[mf][3], ba + ST_ALO + sw);
            }
#pragma unroll
            for (int np = 0; np < 2; np++) {
                int nrow = wn * 32 + np * 16 + lr + (lj & 1) * 8;
                uint32_t sw = SWZ((uint32_t)(nrow * 128 + kf * 32 + (lj >> 1) * 16));
                uint32_t bh[2][2], bl[2][2];
                uint32_t r0, r1, r2, r3;
                ldsm_x4(r0, r1, r2, r3, ba + ST_BHI + sw);
                bh[0][0] = r0; bh[0][1] = r2; bh[1][0] = r1; bh[1][1] = r3;
                ldsm_x4(r0, r1, r2, r3, ba + ST_BLO + sw);
                bl[0][0] = r0; bl[0][1] = r2; bl[1][0] = r1; bl[1][1] = r3;
#pragma unroll
                for (int mf = 0; mf < 2; mf++)
#pragma unroll
                    for (int sub = 0; sub < 2; sub++) {
                        int nf = np * 2 + sub;
                        mma_bf16(acc[mf][nf], a_hi[mf], bh[sub]);
                        mma_bf16(acc[mf][nf], a_hi[mf], bl[sub]);
                        mma_bf16(acc[mf][nf], a_lo[mf], bh[sub]);
                    }
            }
        }
    };

    fill(0, 0);
    CP_COMMIT();
    for (int ch = 0; ch < nch; ch++) {
        int cur = ch & 1;
        CP_WAIT0();
        __syncthreads();
        if (ch + 1 < nch) { fill(cur ^ 1, ch + 1); CP_COMMIT(); }
        compute(cur);
    }

    // ---- epilogue ----------------------------------------------------------
    const int er = bm + wm * 32 + (lid >> 2);
    const int ec = ncol + wn * 32 + (lid & 3) * 2;
#pragma unroll
    for (int mf = 0; mf < 2; mf++) {
        int r0 = er + mf * 16;
#pragma unroll
        for (int nf = 0; nf < 4; nf++) {
            int c = ec + nf * 8;
            if (r0 < M) {
                ep(r0, c, acc[mf][nf][0]);
                ep(r0, c + 1, acc[mf][nf][1]);
            }
            if (r0 + 8 < M) {
                ep(r0 + 8, c, acc[mf][nf][2]);
                ep(r0 + 8, c + 1, acc[mf][nf][3]);
            }
        }
    }
}

// ==================== aggregation / combine / segmean =======================
__global__ __launch_bounds__(256) void aggregate_k(const float* __restrict__ msg,
                                                   const int* __restrict__ a2b,
                                                   float* __restrict__ amsg) {
    int i = blockIdx.x * blockDim.x + threadIdx.x;
    if (i >= NA * (H / 4)) return;
    int a = i >> 6;
    int c = (i & 63) * 4;
    const int* nb = &a2b[a * MAXNB];
    float4 s = make_float4(0.f, 0.f, 0.f, 0.f);
#pragma unroll
    for (int j = 0; j < MAXNB; j++) {
        float4 v = *(const float4*)&msg[(long long)nb[j] * H + c];
        s.x += v.x; s.y += v.y; s.z += v.z; s.w += v.w;
    }
    *(float4*)&amsg[(long long)a * H + c] = s;
}

// msg[b] = relu(inputs[b] + aggP[b2a[b]] - P[b2revb[b]])   (in-place safe)
__global__ __launch_bounds__(256) void combine_k(const float* __restrict__ inputs,
                                                 const float* __restrict__ aggP,
                                                 const float* __restrict__ P,
                                                 const int* __restrict__ b2a,
                                                 const int* __restrict__ b2revb,
                                                 float* __restrict__ msg) {
    int i = blockIdx.x * blockDim.x + threadIdx.x;
    if (i >= NBND * (H / 4)) return;
    int b = i >> 6;
    int c = (i & 63) * 4;
    int ra = b2a[b];
    int rb = b2revb[b];
    float4 vi = *(const float4*)&inputs[(long long)b * H + c];
    float4 va = *(const float4*)&aggP[(long long)ra * H + c];
    float4 vp = *(const float4*)&P[(long long)rb * H + c];
    float4 o;
    o.x = fmaxf(vi.x + va.x - vp.x, 0.f);
    o.y = fmaxf(vi.y + va.y - vp.y, 0.f);
    o.z = fmaxf(vi.z + va.z - vp.z, 0.f);
    o.w = fmaxf(vi.w + va.w - vp.w, 0.f);
    *(float4*)&msg[(long long)b * H + c] = o;
}

__device__ __forceinline__ int lower_bound_i(const int* __restrict__ a, int n, int v) {
    int lo = 0, hi = n;
    while (lo < hi) { int mid = (lo + hi) >> 1; if (a[mid] < v) lo = mid + 1; else hi = mid; }
    return lo;
}
__global__ __launch_bounds__(256) void segmean_k(const float* __restrict__ atomh,
                                                 const int* __restrict__ atom2mol,
                                                 const float* __restrict__ molfeat,
                                                 float* __restrict__ molx) {
    int m = blockIdx.x;
    int tid = threadIdx.x;
    int start = lower_bound_i(atom2mol, NA, m);
    int end = lower_bound_i(atom2mol, NA, m + 1);
    float inv = 1.f / (float)max(end - start, 1);
    float s = 0.f;
    for (int a = start; a < end; a++) s += atomh[(long long)a * H + tid];
    molx[(long long)m * XDIM + tid] = s * inv;
    if (tid < MF) molx[(long long)m * XDIM + H + tid] = molfeat[(long long)m * MF + tid];
}

// ==================== launch ================================================
extern "C" void kernel_launch(void* const* d_in, const int* in_sizes, int n_in,
                              void* d_out, int out_size) {
    (void)in_sizes; (void)n_in; (void)out_size;
    const float* f_atoms  = (const float*)d_in[0];
    const float* f_bonds  = (const float*)d_in[1];
    const int*   a2b      = (const int*)d_in[2];
    const int*   b2a      = (const int*)d_in[3];
    const int*   b2revb   = (const int*)d_in[4];
    const int*   atom2mol = (const int*)d_in[5];
    const float* mol_feat = (const float*)d_in[6];
    const float* W_i      = (const float*)d_in[7];
    const float* W_h      = (const float*)d_in[8];
    const float* W_o_w    = (const float*)d_in[9];
    const float* W_o_b    = (const float*)d_in[10];
    const float* W1       = (const float*)d_in[11];
    const float* b1       = (const float*)d_in[12];
    const float* W2       = (const float*)d_in[13];
    const float* b2       = (const float*)d_in[14];
    float* out = (float*)d_out;

    float *p_inputs, *p_msgA, *p_P, *p_amsg, *p_atomh, *p_molx, *p_h1;
    cudaGetSymbolAddress((void**)&p_inputs, g_inputs);
    cudaGetSymbolAddress((void**)&p_msgA, g_msgA);
    cudaGetSymbolAddress((void**)&p_P, g_P);
    cudaGetSymbolAddress((void**)&p_amsg, g_amsg);
    cudaGetSymbolAddress((void**)&p_atomh, g_atomh);
    cudaGetSymbolAddress((void**)&p_molx, g_molx);
    cudaGetSymbolAddress((void**)&p_h1, g_h1);
    __nv_bfloat16 *wi_h, *wi_l, *wh_h, *wh_l, *wo_h, *wo_l, *w1_h, *w1_l, *w2_h, *w2_l;
    cudaGetSymbolAddress((void**)&wi_h, g_wi_h); cudaGetSymbolAddress((void**)&wi_l, g_wi_l);
    cudaGetSymbolAddress((void**)&wh_h, g_wh_h); cudaGetSymbolAddress((void**)&wh_l, g_wh_l);
    cudaGetSymbolAddress((void**)&wo_h, g_wo_h); cudaGetSymbolAddress((void**)&wo_l, g_wo_l);
    cudaGetSymbolAddress((void**)&w1_h, g_w1_h); cudaGetSymbolAddress((void**)&w1_l, g_w1_l);
    cudaGetSymbolAddress((void**)&w2_h, g_w2_h); cudaGetSymbolAddress((void**)&w2_l, g_w2_l);

    cudaFuncSetAttribute(tc_gemm<TCDirect, EpiBond>, cudaFuncAttributeMaxDynamicSharedMemorySize, SM_TOTAL);
    cudaFuncSetAttribute(tc_gemm<TCDirect, EpiStore>, cudaFuncAttributeMaxDynamicSharedMemorySize, SM_TOTAL);
    cudaFuncSetAttribute(tc_gemm<TCConcat, EpiBias>, cudaFuncAttributeMaxDynamicSharedMemorySize, SM_TOTAL);
    cudaFuncSetAttribute(tc_gemm<TCDirect, EpiBias>, cudaFuncAttributeMaxDynamicSharedMemorySize, SM_TOTAL);

    dim3 blk(256);

    // 0) prep weights (transpose + pad + bf16 hi/lo split)
    prep_w<<<(H * KP_WI + 255) / 256, blk>>>(W_i, wi_h, wi_l, BF, H, KP_WI);
    prep_w<<<(H * KP_WH + 255) / 256, blk>>>(W_h, wh_h, wh_l, H, H, KP_WH);
    prep_w<<<(H * KP_WO + 255) / 256, blk>>>(W_o_w, wo_h, wo_l, AF + H, H, KP_WO);
    prep_w<<<(F1 * KP_W1 + 255) / 256, blk>>>(W1, w1_h, w1_l, XDIM, F1, KP_W1);
    prep_w<<<(F2 * KP_W2 + 255) / 256, blk>>>(W2, w2_h, w2_l, F1, F2, KP_W2);

    const int MB_BND = (NBND + 63) / 64;   // 3125
    const int MB_A   = (NA + 63) / 64;     // 1563
    const int aggBlocks = (NA * (H / 4) + 255) / 256;
    const int cmbBlocks = (NBND * (H / 4) + 255) / 256;

    // 1) inputs = f_bonds @ W_i ; msgA = relu(inputs)
    tc_gemm<<<dim3(MB_BND, H / 128), blk, SM_TOTAL>>>(TCDirect{f_bonds, BF, BF},
        EpiBond{p_inputs, p_msgA}, wi_h, wi_l, NBND, KP_WI);

    // 2-3) two message-passing iterations via linearity:
    //   P = msg @ W_h ; aggP[a] = sum_j P[a2b[a,j]] ;
    //   msg = relu(inputs + aggP[b2a] - P[b2revb])
    for (int it = 0; it < 2; it++) {
        tc_gemm<<<dim3(MB_BND, H / 128), blk, SM_TOTAL>>>(TCDirect{p_msgA, H, H},
            EpiStore{p_P}, wh_h, wh_l, NBND, KP_WH);
        aggregate_k<<<aggBlocks, blk>>>(p_P, a2b, p_amsg);
        combine_k<<<cmbBlocks, blk>>>(p_inputs, p_amsg, p_P, b2a, b2revb, p_msgA);
    }

    // 4) final aggregation + atom readout
    aggregate_k<<<aggBlocks, blk>>>(p_msgA, a2b, p_amsg);
    tc_gemm<<<dim3(MB_A, H / 128), blk, SM_TOTAL>>>(TCConcat{f_atoms, p_amsg},
        EpiBias{W_o_b, p_atomh, H}, wo_h, wo_l, NA, KP_WO);

    // 5) per-molecule mean + feature concat
    segmean_k<<<NM, blk>>>(p_atomh, atom2mol, mol_feat, p_molx);

    // 6) FFNN layer 1: h1 = relu(molx @ W1 + b1)
    tc_gemm<<<dim3(NM / 64, F1 / 128), blk, SM_TOTAL>>>(TCDirect{p_molx, XDIM, XDIM},
        EpiBias{b1, p_h1, F1}, w1_h, w1_l, NM, KP_W1);

    // 7) FFNN layer 2: out = relu(h1 @ W2 + b2)
    tc_gemm<<<dim3(NM / 64, F2 / 128), blk, SM_TOTAL>>>(TCDirect{p_h1, F1, F1},
        EpiBias{b2, out, F2}, w2_h, w2_l, NM, KP_W2);
}